// round 5
// baseline (speedup 1.0000x reference)
#include <cuda_runtime.h>

#define NB   16
#define NH   16
#define SQL  1024
#define SKVL 1024
#define DH   64
#define EMB  1024
#define QT   16
#define KT   64
#define NTHR 256
#define EPITCH 1025   // E row pitch (bank-conflict-free column reads)
#define KPITCH 68     // K/V/O tile row pitch (pad 4 floats)

__device__ __forceinline__ float fast_tanh(float x) {
    float y;
    asm("tanh.approx.f32 %0, %1;" : "=f"(y) : "f"(x));
    return y;
}

__global__ __launch_bounds__(NTHR, 1)
void attn_fused_kernel(const float* __restrict__ Qg, const float* __restrict__ Kg,
                       const float* __restrict__ Vg, const int* __restrict__ maskg,
                       float* __restrict__ outg, float* __restrict__ wg)
{
    extern __shared__ float sm[];
    float* Wacc   = sm;                       // QT*SKVL   (64 KB)
    float* Em     = Wacc + QT*SKVL;           // QT*EPITCH (65.6 KB)
    float* Ks     = Em + QT*EPITCH;           // 2*KT*KPITCH
    float* Vs     = Ks + 2*KT*KPITCH;         // 2*KT*KPITCH
    float* Os     = Vs + 2*KT*KPITCH;         // QT*KPITCH
    float* mfull  = Os + QT*KPITCH;           // SKVL (4 KB)
    float* rowsum = mfull + SKVL;             // QT
    float* invs   = rowsum + QT;              // QT

    const int t  = threadIdx.x;
    const int qi = t & 15;     // q row owned by this thread
    const int g  = t >> 4;     // k-group (S phase) / d-group (AV phase)
    const int b  = blockIdx.y;
    const int q0 = blockIdx.x * QT;

    for (int i = t; i < QT*SKVL; i += NTHR) Wacc[i] = 0.0f;
    for (int i = t; i < SKVL; i += NTHR)
        mfull[i] = (maskg[b*SKVL + i] != 0) ? 0.0f : 1.0f;   // mask is int32 (bool -> int32)

    for (int h = 0; h < NH; h++) {
        // ---- Q row for this thread's q into registers
        float qr[DH];
        {
            const float* qp = Qg + ((size_t)(b*SQL + q0 + qi))*EMB + h*DH;
            #pragma unroll
            for (int i = 0; i < DH/4; i++) {
                float4 v = *(const float4*)(qp + i*4);
                qr[i*4+0]=v.x; qr[i*4+1]=v.y; qr[i*4+2]=v.z; qr[i*4+3]=v.w;
            }
        }
        float oacc0=0.f, oacc1=0.f, oacc2=0.f, oacc3=0.f;
        float psum = 0.0f;
        if (t < QT) rowsum[t] = 0.0f;

        // ---- load kv tile 0 into buffer 0
        {
            const float* kb = Kg + ((size_t)(b*SKVL))*EMB + h*DH;
            const float* vb = Vg + ((size_t)(b*SKVL))*EMB + h*DH;
            #pragma unroll
            for (int i = 0; i < 4; i++) {
                int idx = t + i*NTHR;
                int row = idx >> 4, c4 = (idx & 15)*4;
                *(float4*)(Ks + row*KPITCH + c4) = *(const float4*)(kb + (size_t)row*EMB + c4);
                *(float4*)(Vs + row*KPITCH + c4) = *(const float4*)(vb + (size_t)row*EMB + c4);
            }
        }
        __syncthreads();

        for (int kt = 0; kt < SKVL/KT; kt++) {
            const int cur = kt & 1;
            // ---- prefetch next tile into registers (latency overlaps compute)
            float4 kpre[4], vpre[4];
            if (kt < SKVL/KT - 1) {
                const int kv0 = (kt+1)*KT;
                const float* kb = Kg + ((size_t)(b*SKVL + kv0))*EMB + h*DH;
                const float* vb = Vg + ((size_t)(b*SKVL + kv0))*EMB + h*DH;
                #pragma unroll
                for (int i = 0; i < 4; i++) {
                    int idx = t + i*NTHR;
                    int row = idx >> 4, c4 = (idx & 15)*4;
                    kpre[i] = *(const float4*)(kb + (size_t)row*EMB + c4);
                    vpre[i] = *(const float4*)(vb + (size_t)row*EMB + c4);
                }
            }

            // ---- S phase: thread computes s for (qi, k = kt*64 + g*4 + 0..3)
            {
                const float* kbase = Ks + cur*(KT*KPITCH) + (g*4)*KPITCH;
                float a0=0.f,a1=0.f,a2=0.f,a3=0.f;
                #pragma unroll
                for (int d4 = 0; d4 < DH/4; d4++) {
                    float4 k0 = *(const float4*)(kbase + 0*KPITCH + d4*4);
                    float4 k1 = *(const float4*)(kbase + 1*KPITCH + d4*4);
                    float4 k2 = *(const float4*)(kbase + 2*KPITCH + d4*4);
                    float4 k3 = *(const float4*)(kbase + 3*KPITCH + d4*4);
                    float x0=qr[d4*4+0], x1=qr[d4*4+1], x2=qr[d4*4+2], x3=qr[d4*4+3];
                    a0 += x0*k0.x + x1*k0.y + x2*k0.z + x3*k0.w;
                    a1 += x0*k1.x + x1*k1.y + x2*k1.z + x3*k1.w;
                    a2 += x0*k2.x + x1*k2.y + x2*k2.z + x3*k2.w;
                    a3 += x0*k3.x + x1*k3.y + x2*k3.z + x3*k3.w;
                }
                float* erow = Em + qi*EPITCH + kt*KT + g*4;
                const float* mrow = mfull + kt*KT + g*4;
                float aa[4] = {a0,a1,a2,a3};
                #pragma unroll
                for (int i = 0; i < 4; i++) {
                    float th = fast_tanh(aa[i] * 0.125f);   // scale = 1/sqrt(64)
                    float p = __expf(10.0f * th) * mrow[i]; // bounded -> no max-shift
                    erow[i] = p;
                    psum += p;
                }
            }
            __syncthreads();

            // ---- AV phase: thread accumulates O[qi][g*4 .. g*4+3]
            {
                const float* erow  = Em + qi*EPITCH + kt*KT;
                const float* vbase = Vs + cur*(KT*KPITCH) + g*4;
                #pragma unroll 16
                for (int k = 0; k < KT; k++) {
                    float e = erow[k];
                    float4 vv = *(const float4*)(vbase + k*KPITCH);
                    oacc0 += e*vv.x; oacc1 += e*vv.y; oacc2 += e*vv.z; oacc3 += e*vv.w;
                }
            }

            // ---- commit prefetched tile to the other buffer
            if (kt < SKVL/KT - 1) {
                const int nxt = cur ^ 1;
                #pragma unroll
                for (int i = 0; i < 4; i++) {
                    int idx = t + i*NTHR;
                    int row = idx >> 4, c4 = (idx & 15)*4;
                    *(float4*)(Ks + nxt*(KT*KPITCH) + row*KPITCH + c4) = kpre[i];
                    *(float4*)(Vs + nxt*(KT*KPITCH) + row*KPITCH + c4) = vpre[i];
                }
            }
            __syncthreads();
        }

        // ---- head epilogue
        atomicAdd(&rowsum[qi], psum);
        __syncthreads();
        if (t < QT) invs[t] = 1.0f / rowsum[t];
        __syncthreads();
        {
            float inv = invs[qi];
            float4 o4 = make_float4(oacc0*inv, oacc1*inv, oacc2*inv, oacc3*inv);
            *(float4*)(Os + qi*KPITCH + g*4) = o4;
        }
        __syncthreads();
        // coalesced O write
        for (int i = t; i < QT*DH; i += NTHR) {
            int qq = i >> 6, dd = i & 63;
            outg[((size_t)(b*SQL + q0 + qq))*EMB + h*DH + dd] = Os[qq*KPITCH + dd];
        }
        // accumulate head-average weights in shared (unnormalized by NH)
        for (int i = t; i < QT*SKVL; i += NTHR) {
            int qq = i >> 10, kk = i & 1023;
            Wacc[i] += Em[qq*EPITCH + kk] * invs[qq];
        }
        __syncthreads();
    }

    // ---- final weights write (coalesced), apply 1/NH here
    for (int i = t; i < QT*SKVL; i += NTHR) {
        int qq = i >> 10, kk = i & 1023;
        wg[((size_t)(b*SQL + q0 + qq))*SKVL + kk] = Wacc[i] * (1.0f/NH);
    }
}

extern "C" void kernel_launch(void* const* d_in, const int* in_sizes, int n_in,
                              void* d_out, int out_size)
{
    const float* Q = (const float*)d_in[0];
    const float* K = (const float*)d_in[1];
    const float* V = (const float*)d_in[2];
    const int*   mask = (const int*)d_in[3];   // bool -> int32 per harness dtype set
    // d_in[4] = numb_heads (compile-time constant 16)

    float* out = (float*)d_out;                          // attn_output: 16*1024*1024
    float* w   = out + (size_t)NB * SQL * EMB;           // attn_weights: 16*1024*1024

    size_t smem = (size_t)(QT*SKVL + QT*EPITCH + 4*KT*KPITCH + QT*KPITCH + SKVL + 2*QT) * sizeof(float);
    cudaFuncSetAttribute(attn_fused_kernel, cudaFuncAttributeMaxDynamicSharedMemorySize, (int)smem);

    dim3 grid(SQL/QT, NB);
    attn_fused_kernel<<<grid, NTHR, smem>>>(Q, K, V, mask, out, w);
}